// round 6
// baseline (speedup 1.0000x reference)
#include <cuda_runtime.h>
#include <cuda_bf16.h>
#include <cuda_fp16.h>
#include <cuda_fp8.h>
#include <cstdint>

#define BDIM 2
#define LNUM 6
#define CDIM 128
#define NDIM 4096
#define NT 32
#define BL (BDIM*LNUM)
#define INV_SQRT (1.0f/64.0f)
#define GSCALE 4096.0f               // power-of-2 prescale for Ga (exact to remove)

// ---------------- scratch (static device memory; allocation-free) ----------
__device__ uint8_t g_Qb[(size_t)BL*NDIM*CDIM];          // [bl][n][c] fp8 e4m3
__device__ uint8_t g_Kb[(size_t)BL*NDIM*CDIM];          // [bl][m][c] fp8 e4m3
__device__ __nv_bfloat16 g_Gt[(size_t)BL*CDIM*NDIM];    // [bl][c][m] bf16 (pre-alpha)
__device__ uint8_t g_Ga[(size_t)BL*CDIM*NDIM];          // [bl][c][m] fp8: g*alpha*4096
__device__ uint8_t g_Sb[(size_t)BL*NDIM*NDIM];          // [bl][n][m] fp8: e = exp(s/64)
__device__ float g_psum[(size_t)BL*NDIM*NT];            // partial sum_n e per (m, ntile)
__device__ float g_alpha[(size_t)BL*NDIM];              // 1/Z per m
__device__ float g_acc[(size_t)BL*2*CDIM*NDIM];         // per-(layer,split) out [c][n], x4096

// ---------------- helpers ----------------------------------------------------
__device__ __forceinline__ uint32_t smem_u32(const void* p) {
    uint32_t a;
    asm("{ .reg .u64 t; cvta.to.shared.u64 t, %1; cvt.u32.u64 %0, t; }" : "=r"(a) : "l"(p));
    return a;
}

// swizzled byte offset inside [128 rows][128B] tile: chunk = 16B unit (0..7)
__device__ __forceinline__ uint32_t SWZ8(int row, int chunk) {
    return (uint32_t)row * 128u + (uint32_t)((chunk ^ (row & 7)) << 4);
}

__device__ __forceinline__ void ldmx4(uint32_t* r, uint32_t addr) {
    asm volatile("ldmatrix.sync.aligned.m8n8.x4.shared.b16 {%0,%1,%2,%3}, [%4];"
        : "=r"(r[0]), "=r"(r[1]), "=r"(r[2]), "=r"(r[3]) : "r"(addr));
}

// fp8 e4m3 MMA: D[16x8] += A[16x32] * B[8x32]^T
__device__ __forceinline__ void mma_fp8(float* d, const uint32_t* a, uint32_t b0, uint32_t b1) {
    asm volatile("mma.sync.aligned.m16n8k32.row.col.f32.e4m3.e4m3.f32 "
        "{%0,%1,%2,%3}, {%4,%5,%6,%7}, {%8,%9}, {%0,%1,%2,%3};"
        : "+f"(d[0]), "+f"(d[1]), "+f"(d[2]), "+f"(d[3])
        : "r"(a[0]), "r"(a[1]), "r"(a[2]), "r"(a[3]), "r"(b0), "r"(b1));
}

#define CP_ASYNC16(dst, src) \
    asm volatile("cp.async.cg.shared.global [%0], [%1], 16;" :: "r"(dst), "l"(src))
#define CP_COMMIT() asm volatile("cp.async.commit_group;" ::: "memory")
#define CP_WAIT(n)  asm volatile("cp.async.wait_group %0;" :: "n"(n) : "memory")

__device__ __forceinline__ uint8_t to_e4m3(float x) {
    return (uint8_t)__nv_cvt_float_to_fp8(x, __NV_SATFINITE, __NV_E4M3);
}
__device__ __forceinline__ float from_e4m3(uint8_t b) {
    __half_raw hr = __nv_cvt_fp8_to_halfraw((__nv_fp8_storage_t)b, __NV_E4M3);
    return __half2float(*(__half*)&hr);
}

// ---------------- kernel 1: projections -> fp8 Q, K ; bf16 Gt ---------------
__global__ void proj_kernel(const float* __restrict__ X,
                            const float* __restrict__ W1, const float* __restrict__ b1,
                            const float* __restrict__ W2, const float* __restrict__ b2,
                            const float* __restrict__ Wg, const float* __restrict__ bg)
{
    int bl = blockIdx.z;
    int b  = bl / LNUM;
    int l  = bl % LNUM;
    int p  = blockIdx.y;
    int n0 = blockIdx.x * 64;

    const float* W; const float* bias;
    if (p == 0)      { W = W1; bias = b1; }
    else if (p == 1) { W = W2; bias = b2; }
    else             { W = Wg; bias = bg; }
    W    += (size_t)l * CDIM * CDIM;
    bias += l * CDIM;
    const float* Xb = X + (size_t)b * CDIM * NDIM;

    __shared__ float xs[32][64 + 1];
    __shared__ float ws[32][CDIM + 4];

    int tid = threadIdx.x;
    int tx = tid & 15;
    int ty = tid >> 4;

    float acc[4][8];
    #pragma unroll
    for (int i = 0; i < 4; i++)
        #pragma unroll
        for (int j = 0; j < 8; j++) acc[i][j] = 0.f;

    for (int c0 = 0; c0 < CDIM; c0 += 32) {
        for (int i = tid; i < 32 * 64; i += 256) {
            int c = i >> 6, n = i & 63;
            xs[c][n] = Xb[(size_t)(c0 + c) * NDIM + n0 + n];
        }
        for (int i = tid; i < 32 * CDIM; i += 256) {
            int o = i >> 5, c = i & 31;
            ws[c][o] = W[o * CDIM + c0 + c];
        }
        __syncthreads();
        #pragma unroll
        for (int c = 0; c < 32; c++) {
            float a[4], bb[8];
            #pragma unroll
            for (int i = 0; i < 4; i++) a[i] = xs[c][ty * 4 + i];
            #pragma unroll
            for (int j = 0; j < 8; j++) bb[j] = ws[c][tx * 8 + j];
            #pragma unroll
            for (int i = 0; i < 4; i++)
                #pragma unroll
                for (int j = 0; j < 8; j++) acc[i][j] += a[i] * bb[j];
        }
        __syncthreads();
    }

    if (p < 2) {
        uint8_t* dst = (p == 0 ? g_Qb : g_Kb) + (size_t)bl * NDIM * CDIM;
        #pragma unroll
        for (int i = 0; i < 4; i++) {
            int n = n0 + ty * 4 + i;
            uint64_t pk = 0;
            #pragma unroll
            for (int j = 0; j < 8; j++)
                pk |= (uint64_t)to_e4m3(acc[i][j] + bias[tx * 8 + j]) << (8 * j);
            *(uint64_t*)(dst + (size_t)n * CDIM + tx * 8) = pk;
        }
    } else {
        __nv_bfloat16* dst = g_Gt + (size_t)bl * CDIM * NDIM;   // [c][n]
        #pragma unroll
        for (int i = 0; i < 4; i++) {
            int n = n0 + ty * 4 + i;
            #pragma unroll
            for (int j = 0; j < 8; j++) {
                int o = tx * 8 + j;
                dst[(size_t)o * NDIM + n] = __float2bfloat16(acc[i][j] + bias[o]);
            }
        }
    }
}

// ---------------- kernel 2: fp8 scores -> fp8 e, psum ------------------------
#define SMEM_SCORE (32768 + 1024)
__global__ __launch_bounds__(256) void score_kernel()
{
    extern __shared__ char sm[];
    uint32_t sbA = smem_u32(sm);
    uint32_t sbB = sbA + 16384;
    float* red = (float*)(sm + 32768);

    int tid = threadIdx.x, lane = tid & 31, w = tid >> 5;
    int wn = w >> 2, wm = w & 3;                 // 2(n) x 4(m) warp grid
    int bl = blockIdx.z, m0 = blockIdx.y * 128, n0 = blockIdx.x * 128;

    const uint8_t* Qp = g_Qb + (size_t)bl * NDIM * CDIM;
    const uint8_t* Kp = g_Kb + (size_t)bl * NDIM * CDIM;

    #pragma unroll
    for (int it = 0; it < 4; it++) {
        int s = tid + it * 256;
        int row = s >> 3, ch = s & 7;
        CP_ASYNC16(sbA + SWZ8(row, ch), Qp + (size_t)(n0 + row) * CDIM + ch * 16);
        CP_ASYNC16(sbB + SWZ8(row, ch), Kp + (size_t)(m0 + row) * CDIM + ch * 16);
    }
    CP_COMMIT();
    CP_WAIT(0);
    __syncthreads();

    float acc[4][4][4];
    #pragma unroll
    for (int i = 0; i < 4; i++)
        #pragma unroll
        for (int j = 0; j < 4; j++)
            #pragma unroll
            for (int q = 0; q < 4; q++) acc[i][j][q] = 0.f;

    #pragma unroll
    for (int ks = 0; ks < 4; ks++) {
        uint32_t a[4][4], b[2][4];
        #pragma unroll
        for (int mi = 0; mi < 4; mi++)
            ldmx4(a[mi], sbA + SWZ8(wn * 64 + mi * 16 + (lane & 15), 2 * ks + (lane >> 4)));
        #pragma unroll
        for (int q = 0; q < 2; q++)
            ldmx4(b[q], sbB + SWZ8(wm * 32 + q * 16 + (lane & 7) + ((lane >> 4) << 3),
                                   2 * ks + ((lane >> 3) & 1)));
        #pragma unroll
        for (int mi = 0; mi < 4; mi++)
            #pragma unroll
            for (int q = 0; q < 2; q++) {
                mma_fp8(acc[mi][2 * q],     a[mi], b[q][0], b[q][1]);
                mma_fp8(acc[mi][2 * q + 1], a[mi], b[q][2], b[q][3]);
            }
    }

    int gid = lane >> 2, tig = lane & 3;
    float ss[4][2];
    #pragma unroll
    for (int nj = 0; nj < 4; nj++) { ss[nj][0] = 0.f; ss[nj][1] = 0.f; }

    __syncthreads();   // done reading operand smem; reuse sbA region as e-tile

    // e-tile staging in smem: [128 n-rows][128 m bytes], SWZ8 layout
    #pragma unroll
    for (int mi = 0; mi < 4; mi++) {
        int r0 = wn * 64 + mi * 16 + gid;
        #pragma unroll
        for (int nj = 0; nj < 4; nj++) {
            uint8_t b0 = to_e4m3(__expf(acc[mi][nj][0] * INV_SQRT));
            uint8_t b1 = to_e4m3(__expf(acc[mi][nj][1] * INV_SQRT));
            uint8_t b2 = to_e4m3(__expf(acc[mi][nj][2] * INV_SQRT));
            uint8_t b3 = to_e4m3(__expf(acc[mi][nj][3] * INV_SQRT));
            int mb = wm * 32 + nj * 8 + 2 * tig;
            int chn = mb >> 4, rem = mb & 15;
            *(uint16_t*)(sm + SWZ8(r0, chn) + rem)     = (uint16_t)(b0 | (b1 << 8));
            *(uint16_t*)(sm + SWZ8(r0 + 8, chn) + rem) = (uint16_t)(b2 | (b3 << 8));
            // psum from ROUNDED values for exact softmax consistency
            ss[nj][0] += from_e4m3(b0) + from_e4m3(b2);
            ss[nj][1] += from_e4m3(b1) + from_e4m3(b3);
        }
    }

    // reduce over gid (lanes sharing tig)
    #pragma unroll
    for (int nj = 0; nj < 4; nj++) {
        #pragma unroll
        for (int off = 4; off < 32; off <<= 1) {
            ss[nj][0] += __shfl_xor_sync(0xffffffffu, ss[nj][0], off);
            ss[nj][1] += __shfl_xor_sync(0xffffffffu, ss[nj][1], off);
        }
    }
    if (lane < 4) {
        #pragma unroll
        for (int nj = 0; nj < 4; nj++) {
            red[wn * 128 + wm * 32 + nj * 8 + 2 * tig]     = ss[nj][0];
            red[wn * 128 + wm * 32 + nj * 8 + 2 * tig + 1] = ss[nj][1];
        }
    }
    __syncthreads();

    // coalesced Sb store (fp8, 16B per lane)
    uint8_t* Sp = g_Sb + (size_t)bl * NDIM * NDIM;
    #pragma unroll
    for (int it = 0; it < 4; it++) {
        int s = tid + it * 256;
        int row = s >> 3, ch = s & 7;
        *(uint4*)(Sp + (size_t)(n0 + row) * NDIM + m0 + ch * 16) = *(uint4*)(sm + SWZ8(row, ch));
    }
    if (tid < 128)
        g_psum[((size_t)bl * NDIM + m0 + tid) * NT + blockIdx.x] = red[tid] + red[128 + tid];
}

// ---------------- kernel 3: alpha = 1/Z -------------------------------------
__global__ void stats_kernel()
{
    int idx = blockIdx.x * blockDim.x + threadIdx.x;
    if (idx >= BL * NDIM) return;
    const float* ps = g_psum + (size_t)idx * NT;
    float Z = 0.f;
    #pragma unroll
    for (int t = 0; t < NT; t++) Z += ps[t];
    g_alpha[idx] = 1.f / Z;
}

// ---------------- kernel 3b: Ga = fp8(Gt * alpha * 4096) --------------------
__global__ void scale_kernel()
{
    size_t v = (size_t)blockIdx.x * blockDim.x + threadIdx.x;     // 8-elem group
    const size_t nvec = (size_t)BL * CDIM * NDIM / 8;
    if (v >= nvec) return;
    size_t e0 = v * 8;
    size_t bl = e0 / ((size_t)CDIM * NDIM);
    size_t m  = e0 % NDIM;
    const float* al = g_alpha + bl * NDIM + m;
    uint4 u = *(uint4*)(g_Gt + e0);
    __nv_bfloat162* h = (__nv_bfloat162*)&u;
    uint64_t pk = 0;
    #pragma unroll
    for (int j = 0; j < 4; j++) {
        float2 f = __bfloat1622float2(h[j]);
        pk |= (uint64_t)to_e4m3(f.x * (al[2 * j]     * GSCALE)) << (16 * j);
        pk |= (uint64_t)to_e4m3(f.y * (al[2 * j + 1] * GSCALE)) << (16 * j + 8);
    }
    *(uint64_t*)(g_Ga + e0) = pk;
}

// ---------------- kernel 4: acc[c][n] = sum_m Ga[c][m] * e[n][m] -------------
// 3-stage cp.async pipeline over KC=128 fp8 m-chunks; split-k = 2 (blockIdx.z)
#define KC 128
#define NC 16                          // 2048 / KC chunks per CTA
#define STG_BYTES 32768                // 16KB A + 16KB B
#define SMEM_ATT (3 * STG_BYTES)
__global__ __launch_bounds__(256, 2) void attnout_kernel()
{
    extern __shared__ char sm[];
    uint32_t sb = smem_u32(sm);

    int tid = threadIdx.x, lane = tid & 31, w = tid >> 5;
    int wc = w >> 2, wn = w & 3;                 // 2(c) x 4(n) warp grid
    int bl = blockIdx.y, n0 = blockIdx.x * 128;
    int mbase = blockIdx.z * 2048;

    const uint8_t* Gp = g_Ga + (size_t)bl * CDIM * NDIM;
    const uint8_t* Sp = g_Sb + (size_t)bl * NDIM * NDIM;

    int lrow = tid >> 3, lch = tid & 7;          // loader: 32 rows x 8 chunks per iter

    #pragma unroll
    for (int p = 0; p < 3; p++) {
        int mq = mbase + p * KC;
        uint32_t sA = sb + p * STG_BYTES, sB = sA + 16384;
        #pragma unroll
        for (int it = 0; it < 4; it++) {
            int row = lrow + it * 32;
            CP_ASYNC16(sA + SWZ8(row, lch), Gp + (size_t)row * NDIM + mq + lch * 16);
            CP_ASYNC16(sB + SWZ8(row, lch), Sp + (size_t)(n0 + row) * NDIM + mq + lch * 16);
        }
        CP_COMMIT();
    }

    float acc[4][4][4];
    #pragma unroll
    for (int i = 0; i < 4; i++)
        #pragma unroll
        for (int j = 0; j < 4; j++)
            #pragma unroll
            for (int q = 0; q < 4; q++) acc[i][j][q] = 0.f;

    int st = 0;
    for (int chk = 0; chk < NC; chk++) {
        CP_WAIT(2);
        __syncthreads();

        uint32_t sA = sb + st * STG_BYTES, sB = sA + 16384;
        #pragma unroll
        for (int ks = 0; ks < 4; ks++) {
            uint32_t a[4][4], b[2][4];
            #pragma unroll
            for (int mi = 0; mi < 4; mi++)
                ldmx4(a[mi], sA + SWZ8(wc * 64 + mi * 16 + (lane & 15), 2 * ks + (lane >> 4)));
            #pragma unroll
            for (int q = 0; q < 2; q++)
                ldmx4(b[q], sB + SWZ8(wn * 32 + q * 16 + (lane & 7) + ((lane >> 4) << 3),
                                      2 * ks + ((lane >> 3) & 1)));
            #pragma unroll
            for (int mi = 0; mi < 4; mi++)
                #pragma unroll
                for (int q = 0; q < 2; q++) {
                    mma_fp8(acc[mi][2 * q],     a[mi], b[q][0], b[q][1]);
                    mma_fp8(acc[mi][2 * q + 1], a[mi], b[q][2], b[q][3]);
                }
        }
        __syncthreads();

        if (chk + 3 < NC) {
            int mq = mbase + (chk + 3) * KC;
            #pragma unroll
            for (int it = 0; it < 4; it++) {
                int row = lrow + it * 32;
                CP_ASYNC16(sA + SWZ8(row, lch), Gp + (size_t)row * NDIM + mq + lch * 16);
                CP_ASYNC16(sB + SWZ8(row, lch), Sp + (size_t)(n0 + row) * NDIM + mq + lch * 16);
            }
        }
        CP_COMMIT();
        st = (st + 1 == 3) ? 0 : st + 1;
    }

    int gid = lane >> 2, tig = lane & 3;
    float* dstb = g_acc + ((size_t)(bl * 2 + blockIdx.z)) * CDIM * NDIM;
    #pragma unroll
    for (int mi = 0; mi < 4; mi++) {
        int c0 = wc * 64 + mi * 16 + gid;
        #pragma unroll
        for (int nj = 0; nj < 4; nj++) {
            int n = n0 + wn * 32 + nj * 8 + 2 * tig;
            *(float2*)(dstb + (size_t)c0 * NDIM + n)       = make_float2(acc[mi][nj][0], acc[mi][nj][1]);
            *(float2*)(dstb + (size_t)(c0 + 8) * NDIM + n) = make_float2(acc[mi][nj][2], acc[mi][nj][3]);
        }
    }
}

// ---------------- kernel 5: out = x + mean_l(acc)/GSCALE --------------------
__global__ void epilogue_kernel(const float* __restrict__ X, float* __restrict__ out)
{
    size_t idx = (size_t)blockIdx.x * blockDim.x + threadIdx.x;
    const size_t total = (size_t)BDIM * CDIM * NDIM;
    if (idx >= total) return;
    size_t b   = idx / ((size_t)CDIM * NDIM);
    size_t rem = idx % ((size_t)CDIM * NDIM);
    float s = 0.f;
    #pragma unroll
    for (int l = 0; l < LNUM; l++) {
        size_t base = ((size_t)(b * LNUM + l) * 2) * CDIM * NDIM;
        s += g_acc[base + rem] + g_acc[base + (size_t)CDIM * NDIM + rem];
    }
    out[idx] = X[idx] + s * (1.0f / (LNUM * GSCALE));
}

// ---------------- launch -----------------------------------------------------
extern "C" void kernel_launch(void* const* d_in, const int* in_sizes, int n_in,
                              void* d_out, int out_size)
{
    const float* x  = (const float*)d_in[0];
    const float* W1 = (const float*)d_in[1];
    const float* b1 = (const float*)d_in[2];
    const float* W2 = (const float*)d_in[3];
    const float* b2 = (const float*)d_in[4];
    const float* Wg = (const float*)d_in[5];
    const float* bg = (const float*)d_in[6];
    float* out = (float*)d_out;

    cudaFuncSetAttribute(score_kernel,   cudaFuncAttributeMaxDynamicSharedMemorySize, SMEM_SCORE);
    cudaFuncSetAttribute(attnout_kernel, cudaFuncAttributeMaxDynamicSharedMemorySize, SMEM_ATT);

    proj_kernel<<<dim3(NDIM / 64, 3, BL), 256>>>(x, W1, b1, W2, b2, Wg, bg);
    score_kernel<<<dim3(NT, NT, BL), 256, SMEM_SCORE>>>();
    stats_kernel<<<(BL * NDIM + 255) / 256, 256>>>();
    scale_kernel<<<(unsigned)(((size_t)BL * CDIM * NDIM / 8 + 255) / 256), 256>>>();
    attnout_kernel<<<dim3(NT, BL, 2), 256, SMEM_ATT>>>();
    epilogue_kernel<<<(unsigned)(((size_t)BDIM * CDIM * NDIM + 255) / 256), 256>>>(x, out);
}

// round 7
// speedup vs baseline: 1.6150x; 1.6150x over previous
#include <cuda_runtime.h>
#include <cuda_bf16.h>
#include <cstdint>

#define BDIM 2
#define LNUM 6
#define CDIM 128
#define NDIM 4096
#define NT 32
#define BL (BDIM*LNUM)
#define INV_SQRT (1.0f/64.0f)

// ---------------- scratch (static device memory; allocation-free) ----------
__device__ __nv_bfloat16 g_Xt[(size_t)BDIM*NDIM*CDIM];  // [b][n][c] bf16
__device__ __nv_bfloat16 g_Wb[(size_t)3*LNUM*CDIM*CDIM];// [p][l][o][c] bf16
__device__ __nv_bfloat16 g_Qb[(size_t)BL*NDIM*CDIM];    // [bl][n][c]
__device__ __nv_bfloat16 g_Kb[(size_t)BL*NDIM*CDIM];    // [bl][m][c]
__device__ __nv_bfloat16 g_Gt[(size_t)BL*CDIM*NDIM];    // [bl][c][m] (alpha folded in by scale_kernel)
__device__ __nv_bfloat16 g_Sb[(size_t)BL*NDIM*NDIM];    // [bl][n][m] e = exp(s/64)
__device__ float g_psum[(size_t)BL*NDIM*NT];            // partial sum_n e per (m, ntile)
__device__ float g_alpha[(size_t)BL*NDIM];              // 1/Z per m
__device__ float g_acc[(size_t)BL*2*CDIM*NDIM];         // per-(layer,split) output [c][n]

// ---------------- helpers ----------------------------------------------------
__device__ __forceinline__ uint32_t smem_u32(const void* p) {
    uint32_t a;
    asm("{ .reg .u64 t; cvta.to.shared.u64 t, %1; cvt.u32.u64 %0, t; }" : "=r"(a) : "l"(p));
    return a;
}

// swizzled byte offset inside [128 rows][256B] tile: chunk = 16B unit (0..15)
__device__ __forceinline__ uint32_t SWZ(int row, int chunk) {
    return (uint32_t)row * 256u + (uint32_t)((chunk ^ (row & 7)) << 4);
}
// swizzled byte offset inside [128 rows][128B] tile: chunk = 16B unit (0..7)
__device__ __forceinline__ uint32_t SWZ8(int row, int chunk) {
    return (uint32_t)row * 128u + (uint32_t)((chunk ^ (row & 7)) << 4);
}

__device__ __forceinline__ void ldmx4(uint32_t* r, uint32_t addr) {
    asm volatile("ldmatrix.sync.aligned.m8n8.x4.shared.b16 {%0,%1,%2,%3}, [%4];"
        : "=r"(r[0]), "=r"(r[1]), "=r"(r[2]), "=r"(r[3]) : "r"(addr));
}

__device__ __forceinline__ void mma16816(float* d, const uint32_t* a, uint32_t b0, uint32_t b1) {
    asm volatile("mma.sync.aligned.m16n8k16.row.col.f32.bf16.bf16.f32 "
        "{%0,%1,%2,%3}, {%4,%5,%6,%7}, {%8,%9}, {%0,%1,%2,%3};"
        : "+f"(d[0]), "+f"(d[1]), "+f"(d[2]), "+f"(d[3])
        : "r"(a[0]), "r"(a[1]), "r"(a[2]), "r"(a[3]), "r"(b0), "r"(b1));
}

#define CP_ASYNC16(dst, src) \
    asm volatile("cp.async.cg.shared.global [%0], [%1], 16;" :: "r"(dst), "l"(src))
#define CP_COMMIT() asm volatile("cp.async.commit_group;" ::: "memory")
#define CP_WAIT(n)  asm volatile("cp.async.wait_group %0;" :: "n"(n) : "memory")

// ---------------- kernel 0a: X -> Xt bf16 (transpose) -----------------------
__global__ void xt_kernel(const float* __restrict__ X)
{
    __shared__ float t[32][33];
    int b = blockIdx.z, c0 = blockIdx.y * 32, n0 = blockIdx.x * 32;
    int tx = threadIdx.x, ty = threadIdx.y;   // 32 x 8
    const float* Xb = X + (size_t)b * CDIM * NDIM;
    #pragma unroll
    for (int i = 0; i < 4; i++)
        t[ty + 8 * i][tx] = Xb[(size_t)(c0 + ty + 8 * i) * NDIM + n0 + tx];
    __syncthreads();
    __nv_bfloat16* dst = g_Xt + (size_t)b * NDIM * CDIM;
    #pragma unroll
    for (int i = 0; i < 4; i++)
        dst[(size_t)(n0 + ty + 8 * i) * CDIM + c0 + tx] = __float2bfloat16(t[tx][ty + 8 * i]);
}

// ---------------- kernel 0b: weights -> bf16 --------------------------------
__global__ void wcvt_kernel(const float* __restrict__ W1, const float* __restrict__ W2,
                            const float* __restrict__ Wg)
{
    int idx = blockIdx.x * blockDim.x + threadIdx.x;
    const int per = LNUM * CDIM * CDIM;
    if (idx >= 3 * per) return;
    const float* src = (idx < per) ? W1 : (idx < 2 * per) ? W2 : Wg;
    g_Wb[idx] = __float2bfloat16(src[idx % per]);
}

// ---------------- kernel 1: projections via mma.sync ------------------------
// p=0: Q[n][o] = Xt[n,:]·W1[o,:] + b1[o]
// p=1: K[m][o] = Xt[m,:]·W2[o,:] + b2[o]
// p=2: Gt[o][n] = Wg[o,:]·Xt[n,:] + bg[o]
#define SMEM_PROJ 65536
__global__ __launch_bounds__(256) void projmma_kernel(const float* __restrict__ b1,
                                                      const float* __restrict__ b2,
                                                      const float* __restrict__ bg)
{
    extern __shared__ char sm[];
    uint32_t sbA = smem_u32(sm);
    uint32_t sbB = sbA + 32768;

    int tid = threadIdx.x, lane = tid & 31, w = tid >> 5;
    int wn = w >> 2, wm = w & 3;                 // 2(row) x 4(col) warp grid
    int bl = blockIdx.z, p = blockIdx.y, n0 = blockIdx.x * 128;
    int b = bl / LNUM, l = bl % LNUM;

    const __nv_bfloat16* Xp = g_Xt + ((size_t)b * NDIM + n0) * CDIM;
    const __nv_bfloat16* Wp = g_Wb + (size_t)(p * LNUM + l) * CDIM * CDIM;
    const float* bias = ((p == 0) ? b1 : (p == 1) ? b2 : bg) + l * CDIM;

    const __nv_bfloat16* Ap = (p < 2) ? Xp : Wp;
    const __nv_bfloat16* Bp = (p < 2) ? Wp : Xp;

    #pragma unroll
    for (int it = 0; it < 8; it++) {
        int s = tid + it * 256;
        int row = s >> 4, ch = s & 15;
        CP_ASYNC16(sbA + SWZ(row, ch), Ap + (size_t)row * CDIM + ch * 8);
        CP_ASYNC16(sbB + SWZ(row, ch), Bp + (size_t)row * CDIM + ch * 8);
    }
    CP_COMMIT();
    CP_WAIT(0);
    __syncthreads();

    float acc[4][4][4];
    #pragma unroll
    for (int i = 0; i < 4; i++)
        #pragma unroll
        for (int j = 0; j < 4; j++)
            #pragma unroll
            for (int q = 0; q < 4; q++) acc[i][j][q] = 0.f;

    #pragma unroll
    for (int ks = 0; ks < 8; ks++) {
        uint32_t a[4][4], bfrag[2][4];
        #pragma unroll
        for (int mi = 0; mi < 4; mi++)
            ldmx4(a[mi], sbA + SWZ(wn * 64 + mi * 16 + (lane & 15), 2 * ks + (lane >> 4)));
        #pragma unroll
        for (int q = 0; q < 2; q++)
            ldmx4(bfrag[q], sbB + SWZ(wm * 32 + q * 16 + (lane & 7) + ((lane >> 4) << 3),
                                      2 * ks + ((lane >> 3) & 1)));
        #pragma unroll
        for (int mi = 0; mi < 4; mi++)
            #pragma unroll
            for (int q = 0; q < 2; q++) {
                mma16816(acc[mi][2 * q],     a[mi], bfrag[q][0], bfrag[q][1]);
                mma16816(acc[mi][2 * q + 1], a[mi], bfrag[q][2], bfrag[q][3]);
            }
    }

    int gid = lane >> 2, tig = lane & 3;
    __syncthreads();   // all warps done reading operand smem; reuse sbA as out-tile

    #pragma unroll
    for (int mi = 0; mi < 4; mi++) {
        int r0 = wn * 64 + mi * 16 + gid;
        float brow0 = 0.f, brow8 = 0.f;
        if (p == 2) { brow0 = bias[r0]; brow8 = bias[r0 + 8]; }
        #pragma unroll
        for (int nj = 0; nj < 4; nj++) {
            int mc = wm * 32 + nj * 8 + 2 * tig;
            float v0 = acc[mi][nj][0], v1 = acc[mi][nj][1];
            float v2 = acc[mi][nj][2], v3 = acc[mi][nj][3];
            if (p < 2) {
                float bc0 = bias[mc], bc1 = bias[mc + 1];
                v0 += bc0; v1 += bc1; v2 += bc0; v3 += bc1;
            } else {
                v0 += brow0; v1 += brow0; v2 += brow8; v3 += brow8;
            }
            __nv_bfloat162 h01, h23;
            h01.x = __float2bfloat16(v0); h01.y = __float2bfloat16(v1);
            h23.x = __float2bfloat16(v2); h23.y = __float2bfloat16(v3);
            int chn = wm * 4 + nj;
            *(__nv_bfloat162*)(sm + SWZ(r0, chn) + tig * 4)     = h01;
            *(__nv_bfloat162*)(sm + SWZ(r0 + 8, chn) + tig * 4) = h23;
        }
    }
    __syncthreads();

    if (p < 2) {
        __nv_bfloat16* dst = (p == 0 ? g_Qb : g_Kb) + ((size_t)bl * NDIM + n0) * CDIM;
        #pragma unroll
        for (int it = 0; it < 8; it++) {
            int s = tid + it * 256;
            int row = s >> 4, ch = s & 15;
            *(uint4*)(dst + (size_t)row * CDIM + ch * 8) = *(uint4*)(sm + SWZ(row, ch));
        }
    } else {
        __nv_bfloat16* dst = g_Gt + (size_t)bl * CDIM * NDIM;
        #pragma unroll
        for (int it = 0; it < 8; it++) {
            int s = tid + it * 256;
            int row = s >> 4, ch = s & 15;
            *(uint4*)(dst + (size_t)row * NDIM + n0 + ch * 8) = *(uint4*)(sm + SWZ(row, ch));
        }
    }
}

// ---------------- kernel 2: scores via mma.sync ------------------------------
#define SMEM_SCORE (65536 + 1024)
__global__ __launch_bounds__(256) void score_kernel()
{
    extern __shared__ char sm[];
    uint32_t sbA = smem_u32(sm);
    uint32_t sbB = sbA + 32768;
    float* red = (float*)(sm + 65536);

    int tid = threadIdx.x, lane = tid & 31, w = tid >> 5;
    int wn = w >> 2, wm = w & 3;                 // 2 x 4 warp grid
    int bl = blockIdx.z, m0 = blockIdx.y * 128, n0 = blockIdx.x * 128;

    const __nv_bfloat16* Qp = g_Qb + (size_t)bl * NDIM * CDIM;
    const __nv_bfloat16* Kp = g_Kb + (size_t)bl * NDIM * CDIM;

    #pragma unroll
    for (int it = 0; it < 8; it++) {
        int s = tid + it * 256;
        int row = s >> 4, ch = s & 15;
        CP_ASYNC16(sbA + SWZ(row, ch), Qp + (size_t)(n0 + row) * CDIM + ch * 8);
        CP_ASYNC16(sbB + SWZ(row, ch), Kp + (size_t)(m0 + row) * CDIM + ch * 8);
    }
    CP_COMMIT();
    CP_WAIT(0);
    __syncthreads();

    float acc[4][4][4];
    #pragma unroll
    for (int i = 0; i < 4; i++)
        #pragma unroll
        for (int j = 0; j < 4; j++)
            #pragma unroll
            for (int q = 0; q < 4; q++) acc[i][j][q] = 0.f;

    #pragma unroll
    for (int ks = 0; ks < 8; ks++) {
        uint32_t a[4][4], b[2][4];
        #pragma unroll
        for (int mi = 0; mi < 4; mi++)
            ldmx4(a[mi], sbA + SWZ(wn * 64 + mi * 16 + (lane & 15), 2 * ks + (lane >> 4)));
        #pragma unroll
        for (int q = 0; q < 2; q++)
            ldmx4(b[q], sbB + SWZ(wm * 32 + q * 16 + (lane & 7) + ((lane >> 4) << 3),
                                  2 * ks + ((lane >> 3) & 1)));
        #pragma unroll
        for (int mi = 0; mi < 4; mi++)
            #pragma unroll
            for (int q = 0; q < 2; q++) {
                mma16816(acc[mi][2 * q],     a[mi], b[q][0], b[q][1]);
                mma16816(acc[mi][2 * q + 1], a[mi], b[q][2], b[q][3]);
            }
    }

    int gid = lane >> 2, tig = lane & 3;
    float ss[4][2];
    #pragma unroll
    for (int nj = 0; nj < 4; nj++) { ss[nj][0] = 0.f; ss[nj][1] = 0.f; }

    __syncthreads();   // all warps done reading operand smem; reuse sbA as e-tile

    #pragma unroll
    for (int mi = 0; mi < 4; mi++) {
        int r0 = wn * 64 + mi * 16 + gid;
        #pragma unroll
        for (int nj = 0; nj < 4; nj++) {
            float e0 = __expf(acc[mi][nj][0] * INV_SQRT);
            float e1 = __expf(acc[mi][nj][1] * INV_SQRT);
            float e2 = __expf(acc[mi][nj][2] * INV_SQRT);
            float e3 = __expf(acc[mi][nj][3] * INV_SQRT);
            __nv_bfloat162 h01, h23;
            h01.x = __float2bfloat16(e0); h01.y = __float2bfloat16(e1);
            h23.x = __float2bfloat16(e2); h23.y = __float2bfloat16(e3);
            int chn = wm * 4 + nj;
            *(__nv_bfloat162*)(sm + SWZ(r0, chn) + tig * 4)     = h01;
            *(__nv_bfloat162*)(sm + SWZ(r0 + 8, chn) + tig * 4) = h23;
            ss[nj][0] += __bfloat162float(h01.x) + __bfloat162float(h23.x);
            ss[nj][1] += __bfloat162float(h01.y) + __bfloat162float(h23.y);
        }
    }

    #pragma unroll
    for (int nj = 0; nj < 4; nj++) {
        #pragma unroll
        for (int off = 4; off < 32; off <<= 1) {
            ss[nj][0] += __shfl_xor_sync(0xffffffffu, ss[nj][0], off);
            ss[nj][1] += __shfl_xor_sync(0xffffffffu, ss[nj][1], off);
        }
    }
    if (lane < 4) {
        #pragma unroll
        for (int nj = 0; nj < 4; nj++) {
            red[wn * 128 + wm * 32 + nj * 8 + 2 * tig]     = ss[nj][0];
            red[wn * 128 + wm * 32 + nj * 8 + 2 * tig + 1] = ss[nj][1];
        }
    }
    __syncthreads();

    __nv_bfloat16* Sp = g_Sb + (size_t)bl * NDIM * NDIM;
    #pragma unroll
    for (int it = 0; it < 8; it++) {
        int s = tid + it * 256;
        int row = s >> 4, ch = s & 15;
        *(uint4*)(Sp + (size_t)(n0 + row) * NDIM + m0 + ch * 8) = *(uint4*)(sm + SWZ(row, ch));
    }
    if (tid < 128)
        g_psum[((size_t)bl * NDIM + m0 + tid) * NT + blockIdx.x] = red[tid] + red[128 + tid];
}

// ---------------- kernel 3: alpha = 1/Z -------------------------------------
__global__ void stats_kernel()
{
    int idx = blockIdx.x * blockDim.x + threadIdx.x;
    if (idx >= BL * NDIM) return;
    const float* ps = g_psum + (size_t)idx * NT;
    float Z = 0.f;
    #pragma unroll
    for (int t = 0; t < NT; t++) Z += ps[t];
    g_alpha[idx] = 1.f / Z;
}

// ---------------- kernel 3b: fold alpha into Gt (in place) ------------------
__global__ void scale_kernel()
{
    size_t v = (size_t)blockIdx.x * blockDim.x + threadIdx.x;     // uint4 index
    const size_t nvec = (size_t)BL * CDIM * NDIM / 8;
    if (v >= nvec) return;
    size_t e0 = v * 8;
    size_t bl = e0 / ((size_t)CDIM * NDIM);
    size_t m  = e0 % NDIM;
    const float* al = g_alpha + bl * NDIM + m;
    uint4 u = *(uint4*)(g_Gt + e0);
    __nv_bfloat162* h = (__nv_bfloat162*)&u;
    #pragma unroll
    for (int j = 0; j < 4; j++) {
        float2 f = __bfloat1622float2(h[j]);
        h[j].x = __float2bfloat16(f.x * al[2 * j]);
        h[j].y = __float2bfloat16(f.y * al[2 * j + 1]);
    }
    *(uint4*)(g_Gt + e0) = u;
}

// ---------------- kernel 4: acc[c][n] = sum_m Gta[c][m] * e[n][m] ------------
#define KC 64
#define NC 32
#define STG_BYTES 32768
#define SMEM_ATT (3 * STG_BYTES)
__global__ __launch_bounds__(256, 2) void attnout_kernel()
{
    extern __shared__ char sm[];
    uint32_t sb = smem_u32(sm);

    int tid = threadIdx.x, lane = tid & 31, w = tid >> 5;
    int wc = w >> 2, wn = w & 3;
    int bl = blockIdx.y, n0 = blockIdx.x * 128;
    int mbase = blockIdx.z * 2048;

    const __nv_bfloat16* Gp = g_Gt + (size_t)bl * CDIM * NDIM;
    const __nv_bfloat16* Sp = g_Sb + (size_t)bl * NDIM * NDIM;

    int lrow = tid >> 3, lch = tid & 7;

    #pragma unroll
    for (int p = 0; p < 3; p++) {
        int mq = mbase + p * KC;
        uint32_t sA = sb + p * STG_BYTES, sB = sA + 16384;
        #pragma unroll
        for (int it = 0; it < 4; it++) {
            int row = lrow + it * 32;
            CP_ASYNC16(sA + SWZ8(row, lch), Gp + (size_t)row * NDIM + mq + lch * 8);
            CP_ASYNC16(sB + SWZ8(row, lch), Sp + (size_t)(n0 + row) * NDIM + mq + lch * 8);
        }
        CP_COMMIT();
    }

    float acc[4][4][4];
    #pragma unroll
    for (int i = 0; i < 4; i++)
        #pragma unroll
        for (int j = 0; j < 4; j++)
            #pragma unroll
            for (int q = 0; q < 4; q++) acc[i][j][q] = 0.f;

    int st = 0;
    for (int chk = 0; chk < NC; chk++) {
        CP_WAIT(2);
        __syncthreads();

        uint32_t sA = sb + st * STG_BYTES, sB = sA + 16384;
        #pragma unroll
        for (int ks = 0; ks < 4; ks++) {
            uint32_t a[4][4], b[2][4];
            #pragma unroll
            for (int mi = 0; mi < 4; mi++)
                ldmx4(a[mi], sA + SWZ8(wc * 64 + mi * 16 + (lane & 15), 2 * ks + (lane >> 4)));
            #pragma unroll
            for (int q = 0; q < 2; q++)
                ldmx4(b[q], sB + SWZ8(wn * 32 + q * 16 + (lane & 7) + ((lane >> 4) << 3),
                                      2 * ks + ((lane >> 3) & 1)));
            #pragma unroll
            for (int mi = 0; mi < 4; mi++)
                #pragma unroll
                for (int q = 0; q < 2; q++) {
                    mma16816(acc[mi][2 * q],     a[mi], b[q][0], b[q][1]);
                    mma16816(acc[mi][2 * q + 1], a[mi], b[q][2], b[q][3]);
                }
        }
        __syncthreads();

        if (chk + 3 < NC) {
            int mq = mbase + (chk + 3) * KC;
            #pragma unroll
            for (int it = 0; it < 4; it++) {
                int row = lrow + it * 32;
                CP_ASYNC16(sA + SWZ8(row, lch), Gp + (size_t)row * NDIM + mq + lch * 8);
                CP_ASYNC16(sB + SWZ8(row, lch), Sp + (size_t)(n0 + row) * NDIM + mq + lch * 8);
            }
        }
        CP_COMMIT();
        st = (st + 1 == 3) ? 0 : st + 1;
    }

    int gid = lane >> 2, tig = lane & 3;
    float* dstb = g_acc + ((size_t)(bl * 2 + blockIdx.z)) * CDIM * NDIM;
    #pragma unroll
    for (int mi = 0; mi < 4; mi++) {
        int c0 = wc * 64 + mi * 16 + gid;
        #pragma unroll
        for (int nj = 0; nj < 4; nj++) {
            int n = n0 + wn * 32 + nj * 8 + 2 * tig;
            *(float2*)(dstb + (size_t)c0 * NDIM + n)       = make_float2(acc[mi][nj][0], acc[mi][nj][1]);
            *(float2*)(dstb + (size_t)(c0 + 8) * NDIM + n) = make_float2(acc[mi][nj][2], acc[mi][nj][3]);
        }
    }
}

// ---------------- kernel 5: out = x + mean_l(acc) ---------------------------
__global__ void epilogue_kernel(const float* __restrict__ X, float* __restrict__ out)
{
    size_t idx = (size_t)blockIdx.x * blockDim.x + threadIdx.x;
    const size_t total = (size_t)BDIM * CDIM * NDIM;
    if (idx >= total) return;
    size_t b   = idx / ((size_t)CDIM * NDIM);
    size_t rem = idx % ((size_t)CDIM * NDIM);
    float s = 0.f;
    #pragma unroll
    for (int l = 0; l < LNUM; l++) {
        size_t base = ((size_t)(b * LNUM + l) * 2) * CDIM * NDIM;
        s += g_acc[base + rem] + g_acc[base + (size_t)CDIM * NDIM + rem];
    }
    out[idx] = X[idx] + s * (1.0f / LNUM);
}

// ---------------- launch -----------------------------------------------------
extern "C" void kernel_launch(void* const* d_in, const int* in_sizes, int n_in,
                              void* d_out, int out_size)
{
    const float* x  = (const float*)d_in[0];
    const float* W1 = (const float*)d_in[1];
    const float* b1 = (const float*)d_in[2];
    const float* W2 = (const float*)d_in[3];
    const float* b2 = (const float*)d_in[4];
    const float* Wg = (const float*)d_in[5];
    const float* bg = (const float*)d_in[6];
    float* out = (float*)d_out;

    cudaFuncSetAttribute(projmma_kernel, cudaFuncAttributeMaxDynamicSharedMemorySize, SMEM_PROJ);
    cudaFuncSetAttribute(score_kernel,   cudaFuncAttributeMaxDynamicSharedMemorySize, SMEM_SCORE);
    cudaFuncSetAttribute(attnout_kernel, cudaFuncAttributeMaxDynamicSharedMemorySize, SMEM_ATT);

    xt_kernel<<<dim3(NDIM / 32, CDIM / 32, BDIM), dim3(32, 8)>>>(x);
    wcvt_kernel<<<(3 * LNUM * CDIM * CDIM + 255) / 256, 256>>>(W1, W2, Wg);
    projmma_kernel<<<dim3(NT, 3, BL), 256, SMEM_PROJ>>>(b1, b2, bg);
    score_kernel<<<dim3(NT, NT, BL), 256, SMEM_SCORE>>>();
    stats_kernel<<<(BL * NDIM + 255) / 256, 256>>>();
    scale_kernel<<<(unsigned)(((size_t)BL * CDIM * NDIM / 8 + 255) / 256), 256>>>();
    attnout_kernel<<<dim3(NT, BL, 2), 256, SMEM_ATT>>>();
    epilogue_kernel<<<(unsigned)(((size_t)BDIM * CDIM * NDIM + 255) / 256), 256>>>(x, out);
}

// round 8
// speedup vs baseline: 1.6819x; 1.0414x over previous
#include <cuda_runtime.h>
#include <cuda_bf16.h>
#include <cstdint>

#define BDIM 2
#define LNUM 6
#define CDIM 128
#define NDIM 4096
#define NT 32
#define BL (BDIM*LNUM)
#define INV_SQRT (1.0f/64.0f)

// ---------------- scratch (static device memory; allocation-free) ----------
__device__ __nv_bfloat16 g_Xt[(size_t)BDIM*NDIM*CDIM];  // [b][n][c] bf16
__device__ __nv_bfloat16 g_Wb[(size_t)3*LNUM*CDIM*CDIM];// [p][l][o][c] bf16
__device__ __nv_bfloat16 g_Qb[(size_t)BL*NDIM*CDIM];    // [bl][n][c]
__device__ __nv_bfloat16 g_Kb[(size_t)BL*NDIM*CDIM];    // [bl][m][c]
__device__ __nv_bfloat16 g_Gt[(size_t)BL*CDIM*NDIM];    // [bl][c][m] (alpha folded in by scale_kernel)
__device__ __nv_bfloat16 g_Sb[(size_t)BL*NDIM*NDIM];    // [bl][n][m] e = exp(s/64)
__device__ float g_psum[(size_t)BL*NDIM*NT];            // partial sum_n e per (m, ntile)
__device__ float g_alpha[(size_t)BL*NDIM];              // 1/Z per m
__device__ float g_acc[(size_t)BL*2*CDIM*NDIM];         // per-(layer,split) output [c][n]

// ---------------- helpers ----------------------------------------------------
__device__ __forceinline__ uint32_t smem_u32(const void* p) {
    uint32_t a;
    asm("{ .reg .u64 t; cvta.to.shared.u64 t, %1; cvt.u32.u64 %0, t; }" : "=r"(a) : "l"(p));
    return a;
}

// swizzled byte offset inside [128 rows][256B] tile: chunk = 16B unit (0..15)
__device__ __forceinline__ uint32_t SWZ(int row, int chunk) {
    return (uint32_t)row * 256u + (uint32_t)((chunk ^ (row & 7)) << 4);
}
// swizzled byte offset inside [128 rows][128B] tile: chunk = 16B unit (0..7)
__device__ __forceinline__ uint32_t SWZ8(int row, int chunk) {
    return (uint32_t)row * 128u + (uint32_t)((chunk ^ (row & 7)) << 4);
}

__device__ __forceinline__ void ldmx4(uint32_t* r, uint32_t addr) {
    asm volatile("ldmatrix.sync.aligned.m8n8.x4.shared.b16 {%0,%1,%2,%3}, [%4];"
        : "=r"(r[0]), "=r"(r[1]), "=r"(r[2]), "=r"(r[3]) : "r"(addr));
}

__device__ __forceinline__ void mma16816(float* d, const uint32_t* a, uint32_t b0, uint32_t b1) {
    asm volatile("mma.sync.aligned.m16n8k16.row.col.f32.bf16.bf16.f32 "
        "{%0,%1,%2,%3}, {%4,%5,%6,%7}, {%8,%9}, {%0,%1,%2,%3};"
        : "+f"(d[0]), "+f"(d[1]), "+f"(d[2]), "+f"(d[3])
        : "r"(a[0]), "r"(a[1]), "r"(a[2]), "r"(a[3]), "r"(b0), "r"(b1));
}

#define CP_ASYNC16(dst, src) \
    asm volatile("cp.async.cg.shared.global [%0], [%1], 16;" :: "r"(dst), "l"(src))
#define CP_COMMIT() asm volatile("cp.async.commit_group;" ::: "memory")
#define CP_WAIT(n)  asm volatile("cp.async.wait_group %0;" :: "n"(n) : "memory")

// ---------------- kernel 0a: X -> Xt bf16 (transpose) -----------------------
__global__ void xt_kernel(const float* __restrict__ X)
{
    __shared__ float t[32][33];
    int b = blockIdx.z, c0 = blockIdx.y * 32, n0 = blockIdx.x * 32;
    int tx = threadIdx.x, ty = threadIdx.y;   // 32 x 8
    const float* Xb = X + (size_t)b * CDIM * NDIM;
    #pragma unroll
    for (int i = 0; i < 4; i++)
        t[ty + 8 * i][tx] = Xb[(size_t)(c0 + ty + 8 * i) * NDIM + n0 + tx];
    __syncthreads();
    __nv_bfloat16* dst = g_Xt + (size_t)b * NDIM * CDIM;
    #pragma unroll
    for (int i = 0; i < 4; i++)
        dst[(size_t)(n0 + ty + 8 * i) * CDIM + c0 + tx] = __float2bfloat16(t[tx][ty + 8 * i]);
}

// ---------------- kernel 0b: weights -> bf16 --------------------------------
__global__ void wcvt_kernel(const float* __restrict__ W1, const float* __restrict__ W2,
                            const float* __restrict__ Wg)
{
    int idx = blockIdx.x * blockDim.x + threadIdx.x;
    const int per = LNUM * CDIM * CDIM;
    if (idx >= 3 * per) return;
    const float* src = (idx < per) ? W1 : (idx < 2 * per) ? W2 : Wg;
    g_Wb[idx] = __float2bfloat16(src[idx % per]);
}

// ---------------- kernel 1: projections via mma.sync ------------------------
#define SMEM_PROJ 65536
__global__ __launch_bounds__(256) void projmma_kernel(const float* __restrict__ b1,
                                                      const float* __restrict__ b2,
                                                      const float* __restrict__ bg)
{
    extern __shared__ char sm[];
    uint32_t sbA = smem_u32(sm);
    uint32_t sbB = sbA + 32768;

    int tid = threadIdx.x, lane = tid & 31, w = tid >> 5;
    int wn = w >> 2, wm = w & 3;                 // 2(row) x 4(col) warp grid
    int bl = blockIdx.z, p = blockIdx.y, n0 = blockIdx.x * 128;
    int b = bl / LNUM, l = bl % LNUM;

    const __nv_bfloat16* Xp = g_Xt + ((size_t)b * NDIM + n0) * CDIM;
    const __nv_bfloat16* Wp = g_Wb + (size_t)(p * LNUM + l) * CDIM * CDIM;
    const float* bias = ((p == 0) ? b1 : (p == 1) ? b2 : bg) + l * CDIM;

    const __nv_bfloat16* Ap = (p < 2) ? Xp : Wp;
    const __nv_bfloat16* Bp = (p < 2) ? Wp : Xp;

    #pragma unroll
    for (int it = 0; it < 8; it++) {
        int s = tid + it * 256;
        int row = s >> 4, ch = s & 15;
        CP_ASYNC16(sbA + SWZ(row, ch), Ap + (size_t)row * CDIM + ch * 8);
        CP_ASYNC16(sbB + SWZ(row, ch), Bp + (size_t)row * CDIM + ch * 8);
    }
    CP_COMMIT();
    CP_WAIT(0);
    __syncthreads();

    float acc[4][4][4];
    #pragma unroll
    for (int i = 0; i < 4; i++)
        #pragma unroll
        for (int j = 0; j < 4; j++)
            #pragma unroll
            for (int q = 0; q < 4; q++) acc[i][j][q] = 0.f;

    #pragma unroll
    for (int ks = 0; ks < 8; ks++) {
        uint32_t a[4][4], bfrag[2][4];
        #pragma unroll
        for (int mi = 0; mi < 4; mi++)
            ldmx4(a[mi], sbA + SWZ(wn * 64 + mi * 16 + (lane & 15), 2 * ks + (lane >> 4)));
        #pragma unroll
        for (int q = 0; q < 2; q++)
            ldmx4(bfrag[q], sbB + SWZ(wm * 32 + q * 16 + (lane & 7) + ((lane >> 4) << 3),
                                      2 * ks + ((lane >> 3) & 1)));
        #pragma unroll
        for (int mi = 0; mi < 4; mi++)
            #pragma unroll
            for (int q = 0; q < 2; q++) {
                mma16816(acc[mi][2 * q],     a[mi], bfrag[q][0], bfrag[q][1]);
                mma16816(acc[mi][2 * q + 1], a[mi], bfrag[q][2], bfrag[q][3]);
            }
    }

    int gid = lane >> 2, tig = lane & 3;
    __syncthreads();   // all warps done reading operand smem; reuse sbA as out-tile

    #pragma unroll
    for (int mi = 0; mi < 4; mi++) {
        int r0 = wn * 64 + mi * 16 + gid;
        float brow0 = 0.f, brow8 = 0.f;
        if (p == 2) { brow0 = bias[r0]; brow8 = bias[r0 + 8]; }
        #pragma unroll
        for (int nj = 0; nj < 4; nj++) {
            int mc = wm * 32 + nj * 8 + 2 * tig;
            float v0 = acc[mi][nj][0], v1 = acc[mi][nj][1];
            float v2 = acc[mi][nj][2], v3 = acc[mi][nj][3];
            if (p < 2) {
                float bc0 = bias[mc], bc1 = bias[mc + 1];
                v0 += bc0; v1 += bc1; v2 += bc0; v3 += bc1;
            } else {
                v0 += brow0; v1 += brow0; v2 += brow8; v3 += brow8;
            }
            __nv_bfloat162 h01, h23;
            h01.x = __float2bfloat16(v0); h01.y = __float2bfloat16(v1);
            h23.x = __float2bfloat16(v2); h23.y = __float2bfloat16(v3);
            int chn = wm * 4 + nj;
            *(__nv_bfloat162*)(sm + SWZ(r0, chn) + tig * 4)     = h01;
            *(__nv_bfloat162*)(sm + SWZ(r0 + 8, chn) + tig * 4) = h23;
        }
    }
    __syncthreads();

    if (p < 2) {
        __nv_bfloat16* dst = (p == 0 ? g_Qb : g_Kb) + ((size_t)bl * NDIM + n0) * CDIM;
        #pragma unroll
        for (int it = 0; it < 8; it++) {
            int s = tid + it * 256;
            int row = s >> 4, ch = s & 15;
            *(uint4*)(dst + (size_t)row * CDIM + ch * 8) = *(uint4*)(sm + SWZ(row, ch));
        }
    } else {
        __nv_bfloat16* dst = g_Gt + (size_t)bl * CDIM * NDIM;
        #pragma unroll
        for (int it = 0; it < 8; it++) {
            int s = tid + it * 256;
            int row = s >> 4, ch = s & 15;
            *(uint4*)(dst + (size_t)row * NDIM + n0 + ch * 8) = *(uint4*)(sm + SWZ(row, ch));
        }
    }
}

// ---------------- kernel 2: scores v2 — Q-resident, K-pipelined m-loop ------
// CTA: n-tile n0 (Q resident), loops 4 m-tiles (m = blockIdx.y*512 + mi*128)
// smem: Q 32KB | Kstage0 32KB | Kstage1 32KB | red 1KB
#define SMEM_SCORE (98304 + 1024)
__global__ __launch_bounds__(256, 2) void score_kernel()
{
    extern __shared__ char sm[];
    uint32_t sbQ = smem_u32(sm);
    float* red = (float*)(sm + 98304);

    int tid = threadIdx.x, lane = tid & 31, w = tid >> 5;
    int wn = w >> 2, wm = w & 3;                 // 2(n) x 4(m) warp grid
    int bl = blockIdx.z, n0 = blockIdx.x * 128, mg = blockIdx.y * 512;

    const __nv_bfloat16* Qp = g_Qb + (size_t)bl * NDIM * CDIM;
    const __nv_bfloat16* Kp = g_Kb + (size_t)bl * NDIM * CDIM;
    __nv_bfloat16* Sp = g_Sb + (size_t)bl * NDIM * NDIM;

    int lrow = tid >> 4, lch = tid & 15;          // loader: 16 rows x 16 chunks per it

    // group 0: Q tile
    #pragma unroll
    for (int it = 0; it < 8; it++) {
        int row = lrow + it * 16;
        CP_ASYNC16(sbQ + SWZ(row, lch), Qp + (size_t)(n0 + row) * CDIM + lch * 8);
    }
    CP_COMMIT();
    // groups 1,2: K0 -> stage0, K1 -> stage1
    #pragma unroll
    for (int p = 0; p < 2; p++) {
        uint32_t sK = sbQ + 32768 + p * 32768;
        #pragma unroll
        for (int it = 0; it < 8; it++) {
            int row = lrow + it * 16;
            CP_ASYNC16(sK + SWZ(row, lch), Kp + (size_t)(mg + p * 128 + row) * CDIM + lch * 8);
        }
        CP_COMMIT();
    }

    int gid = lane >> 2, tig = lane & 3;

    for (int mi = 0; mi < 4; mi++) {
        CP_WAIT(1);                 // Q + K_mi complete (newest group may be outstanding)
        __syncthreads();

        uint32_t sK = sbQ + 32768 + (mi & 1) * 32768;
        char*   smK = sm + 32768 + (mi & 1) * 32768;
        int m0 = mg + mi * 128;

        float acc[4][4][4];
        #pragma unroll
        for (int i = 0; i < 4; i++)
            #pragma unroll
            for (int j = 0; j < 4; j++)
                #pragma unroll
                for (int q = 0; q < 4; q++) acc[i][j][q] = 0.f;

        #pragma unroll
        for (int ks = 0; ks < 8; ks++) {
            uint32_t a[4][4], b[2][4];
            #pragma unroll
            for (int ni = 0; ni < 4; ni++)
                ldmx4(a[ni], sbQ + SWZ(wn * 64 + ni * 16 + (lane & 15), 2 * ks + (lane >> 4)));
            #pragma unroll
            for (int q = 0; q < 2; q++)
                ldmx4(b[q], sK + SWZ(wm * 32 + q * 16 + (lane & 7) + ((lane >> 4) << 3),
                                     2 * ks + ((lane >> 3) & 1)));
            #pragma unroll
            for (int ni = 0; ni < 4; ni++)
                #pragma unroll
                for (int q = 0; q < 2; q++) {
                    mma16816(acc[ni][2 * q],     a[ni], b[q][0], b[q][1]);
                    mma16816(acc[ni][2 * q + 1], a[ni], b[q][2], b[q][3]);
                }
        }

        __syncthreads();            // all warps done reading K stage; reuse as e-tile

        float ss[4][2];
        #pragma unroll
        for (int nj = 0; nj < 4; nj++) { ss[nj][0] = 0.f; ss[nj][1] = 0.f; }

        #pragma unroll
        for (int ni = 0; ni < 4; ni++) {
            int r0 = wn * 64 + ni * 16 + gid;
            #pragma unroll
            for (int nj = 0; nj < 4; nj++) {
                float e0 = __expf(acc[ni][nj][0] * INV_SQRT);
                float e1 = __expf(acc[ni][nj][1] * INV_SQRT);
                float e2 = __expf(acc[ni][nj][2] * INV_SQRT);
                float e3 = __expf(acc[ni][nj][3] * INV_SQRT);
                __nv_bfloat162 h01, h23;
                h01.x = __float2bfloat16(e0); h01.y = __float2bfloat16(e1);
                h23.x = __float2bfloat16(e2); h23.y = __float2bfloat16(e3);
                int chn = wm * 4 + nj;
                *(__nv_bfloat162*)(smK + SWZ(r0, chn) + tig * 4)     = h01;
                *(__nv_bfloat162*)(smK + SWZ(r0 + 8, chn) + tig * 4) = h23;
                ss[nj][0] += __bfloat162float(h01.x) + __bfloat162float(h23.x);
                ss[nj][1] += __bfloat162float(h01.y) + __bfloat162float(h23.y);
            }
        }

        #pragma unroll
        for (int nj = 0; nj < 4; nj++) {
            #pragma unroll
            for (int off = 4; off < 32; off <<= 1) {
                ss[nj][0] += __shfl_xor_sync(0xffffffffu, ss[nj][0], off);
                ss[nj][1] += __shfl_xor_sync(0xffffffffu, ss[nj][1], off);
            }
        }
        if (lane < 4) {
            #pragma unroll
            for (int nj = 0; nj < 4; nj++) {
                red[wn * 128 + wm * 32 + nj * 8 + 2 * tig]     = ss[nj][0];
                red[wn * 128 + wm * 32 + nj * 8 + 2 * tig + 1] = ss[nj][1];
            }
        }
        __syncthreads();            // e-tile + red complete

        // coalesced Sb store; then reload this stage with K_{mi+2}
        #pragma unroll
        for (int it = 0; it < 8; it++) {
            int row = lrow + it * 16;
            *(uint4*)(Sp + (size_t)(n0 + row) * NDIM + m0 + lch * 8) =
                *(uint4*)(smK + SWZ(row, lch));
        }
        if (tid < 128)
            g_psum[((size_t)bl * NDIM + m0 + tid) * NT + blockIdx.x] = red[tid] + red[128 + tid];

        if (mi + 2 < 4) {
            int mnext = mg + (mi + 2) * 128;
            #pragma unroll
            for (int it = 0; it < 8; it++) {
                int row = lrow + it * 16;
                CP_ASYNC16(sK + SWZ(row, lch), Kp + (size_t)(mnext + row) * CDIM + lch * 8);
            }
        }
        CP_COMMIT();                // commit every iteration to keep group counts aligned
    }
}

// ---------------- kernel 3: alpha = 1/Z -------------------------------------
__global__ void stats_kernel()
{
    int idx = blockIdx.x * blockDim.x + threadIdx.x;
    if (idx >= BL * NDIM) return;
    const float* ps = g_psum + (size_t)idx * NT;
    float Z = 0.f;
    #pragma unroll
    for (int t = 0; t < NT; t++) Z += ps[t];
    g_alpha[idx] = 1.f / Z;
}

// ---------------- kernel 3b: fold alpha into Gt (in place) ------------------
__global__ void scale_kernel()
{
    size_t v = (size_t)blockIdx.x * blockDim.x + threadIdx.x;     // uint4 index
    const size_t nvec = (size_t)BL * CDIM * NDIM / 8;
    if (v >= nvec) return;
    size_t e0 = v * 8;
    size_t bl = e0 / ((size_t)CDIM * NDIM);
    size_t m  = e0 % NDIM;
    const float* al = g_alpha + bl * NDIM + m;
    uint4 u = *(uint4*)(g_Gt + e0);
    __nv_bfloat162* h = (__nv_bfloat162*)&u;
    #pragma unroll
    for (int j = 0; j < 4; j++) {
        float2 f = __bfloat1622float2(h[j]);
        h[j].x = __float2bfloat16(f.x * al[2 * j]);
        h[j].y = __float2bfloat16(f.y * al[2 * j + 1]);
    }
    *(uint4*)(g_Gt + e0) = u;
}

// ---------------- kernel 4: acc[c][n] = sum_m Gta[c][m] * e[n][m] ------------
#define KC 64
#define NC 32
#define STG_BYTES 32768
#define SMEM_ATT (3 * STG_BYTES)
__global__ __launch_bounds__(256, 2) void attnout_kernel()
{
    extern __shared__ char sm[];
    uint32_t sb = smem_u32(sm);

    int tid = threadIdx.x, lane = tid & 31, w = tid >> 5;
    int wc = w >> 2, wn = w & 3;
    int bl = blockIdx.y, n0 = blockIdx.x * 128;
    int mbase = blockIdx.z * 2048;

    const __nv_bfloat16* Gp = g_Gt + (size_t)bl * CDIM * NDIM;
    const __nv_bfloat16* Sp = g_Sb + (size_t)bl * NDIM * NDIM;

    int lrow = tid >> 3, lch = tid & 7;

    #pragma unroll
    for (int p = 0; p < 3; p++) {
        int mq = mbase + p * KC;
        uint32_t sA = sb + p * STG_BYTES, sB = sA + 16384;
        #pragma unroll
        for (int it = 0; it < 4; it++) {
            int row = lrow + it * 32;
            CP_ASYNC16(sA + SWZ8(row, lch), Gp + (size_t)row * NDIM + mq + lch * 8);
            CP_ASYNC16(sB + SWZ8(row, lch), Sp + (size_t)(n0 + row) * NDIM + mq + lch * 8);
        }
        CP_COMMIT();
    }

    float acc[4][4][4];
    #pragma unroll
    for (int i = 0; i < 4; i++)
        #pragma unroll
        for (int j = 0; j < 4; j++)
            #pragma unroll
            for (int q = 0; q < 4; q++) acc[i][j][q] = 0.f;

    int st = 0;
    for (int chk = 0; chk < NC; chk++) {
        CP_WAIT(2);
        __syncthreads();

        uint32_t sA = sb + st * STG_BYTES, sB = sA + 16384;
        #pragma unroll
        for (int ks = 0; ks < 4; ks++) {
            uint32_t a[4][4], b[2][4];
            #pragma unroll
            for (int mi = 0; mi < 4; mi++)
                ldmx4(a[mi], sA + SWZ8(wc * 64 + mi * 16 + (lane & 15), 2 * ks + (lane >> 4)));
            #pragma unroll
            for (int q = 0; q < 2; q++)
                ldmx4(b[q], sB + SWZ8(wn * 32 + q * 16 + (lane & 7) + ((lane >> 4) << 3),
                                      2 * ks + ((lane >> 3) & 1)));
            #pragma unroll
            for (int mi = 0; mi < 4; mi++)
                #pragma unroll
                for (int q = 0; q < 2; q++) {
                    mma16816(acc[mi][2 * q],     a[mi], b[q][0], b[q][1]);
                    mma16816(acc[mi][2 * q + 1], a[mi], b[q][2], b[q][3]);
                }
        }
        __syncthreads();

        if (chk + 3 < NC) {
            int mq = mbase + (chk + 3) * KC;
            #pragma unroll
            for (int it = 0; it < 4; it++) {
                int row = lrow + it * 32;
                CP_ASYNC16(sA + SWZ8(row, lch), Gp + (size_t)row * NDIM + mq + lch * 8);
                CP_ASYNC16(sB + SWZ8(row, lch), Sp + (size_t)(n0 + row) * NDIM + mq + lch * 8);
            }
        }
        CP_COMMIT();
        st = (st + 1 == 3) ? 0 : st + 1;
    }

    int gid = lane >> 2, tig = lane & 3;
    float* dstb = g_acc + ((size_t)(bl * 2 + blockIdx.z)) * CDIM * NDIM;
    #pragma unroll
    for (int mi = 0; mi < 4; mi++) {
        int c0 = wc * 64 + mi * 16 + gid;
        #pragma unroll
        for (int nj = 0; nj < 4; nj++) {
            int n = n0 + wn * 32 + nj * 8 + 2 * tig;
            *(float2*)(dstb + (size_t)c0 * NDIM + n)       = make_float2(acc[mi][nj][0], acc[mi][nj][1]);
            *(float2*)(dstb + (size_t)(c0 + 8) * NDIM + n) = make_float2(acc[mi][nj][2], acc[mi][nj][3]);
        }
    }
}

// ---------------- kernel 5: out = x + mean_l(acc) ---------------------------
__global__ void epilogue_kernel(const float* __restrict__ X, float* __restrict__ out)
{
    size_t idx = (size_t)blockIdx.x * blockDim.x + threadIdx.x;
    const size_t total = (size_t)BDIM * CDIM * NDIM;
    if (idx >= total) return;
    size_t b   = idx / ((size_t)CDIM * NDIM);
    size_t rem = idx % ((size_t)CDIM * NDIM);
    float s = 0.f;
    #pragma unroll
    for (int l = 0; l < LNUM; l++) {
        size_t base = ((size_t)(b * LNUM + l) * 2) * CDIM * NDIM;
        s += g_acc[base + rem] + g_acc[base + (size_t)CDIM * NDIM + rem];
    }
    out[idx] = X[idx] + s * (1.0f / LNUM);
}

// ---------------- launch -----------------------------------------------------
extern "C" void kernel_launch(void* const* d_in, const int* in_sizes, int n_in,
                              void* d_out, int out_size)
{
    const float* x  = (const float*)d_in[0];
    const float* W1 = (const float*)d_in[1];
    const float* b1 = (const float*)d_in[2];
    const float* W2 = (const float*)d_in[3];
    const float* b2 = (const float*)d_in[4];
    const float* Wg = (const float*)d_in[5];
    const float* bg = (const float*)d_in[6];
    float* out = (float*)d_out;

    cudaFuncSetAttribute(projmma_kernel, cudaFuncAttributeMaxDynamicSharedMemorySize, SMEM_PROJ);
    cudaFuncSetAttribute(score_kernel,   cudaFuncAttributeMaxDynamicSharedMemorySize, SMEM_SCORE);
    cudaFuncSetAttribute(attnout_kernel, cudaFuncAttributeMaxDynamicSharedMemorySize, SMEM_ATT);

    xt_kernel<<<dim3(NDIM / 32, CDIM / 32, BDIM), dim3(32, 8)>>>(x);
    wcvt_kernel<<<(3 * LNUM * CDIM * CDIM + 255) / 256, 256>>>(W1, W2, Wg);
    projmma_kernel<<<dim3(NT, 3, BL), 256, SMEM_PROJ>>>(b1, b2, bg);
    score_kernel<<<dim3(NT, 8, BL), 256, SMEM_SCORE>>>();
    stats_kernel<<<(BL * NDIM + 255) / 256, 256>>>();
    scale_kernel<<<(unsigned)(((size_t)BL * CDIM * NDIM / 8 + 255) / 256), 256>>>();
    attnout_kernel<<<dim3(NT, BL, 2), 256, SMEM_ATT>>>();
    epilogue_kernel<<<(unsigned)(((size_t)BDIM * CDIM * NDIM + 255) / 256), 256>>>(x, out);
}